// round 12
// baseline (speedup 1.0000x reference)
#include <cuda_runtime.h>
#include <cuda_bf16.h>
#include <cstdint>
#include <cstddef>

#define BATCH 32
#define SEQ   512
#define ISZ   512
#define HSZ   1024
#define G4    4096
#define NB2   128
#define NT2   256

typedef unsigned long long ull;

// ---------------------------------------------------------------------------
// Device scratch (allocation-free rule: __device__ globals).
// g_Xg : [s][b][4096] input projections + bias, fp32, 256MB.
// g_h  : ping-pong hidden state, natural [b][k] layout.
// g_Upk: per-block image of packed U: [hb][p(512)][cgrp(8)][c(4)] ull,
//        ull = {U[2p][col], U[2p+1][col]}, col = hb*8+(cgrp&1)*4+c,
//        gate = cgrp>>1. 16MB. Block hb copies its contiguous 128KB once.
// ---------------------------------------------------------------------------
__device__ float    g_Xg[(size_t)SEQ * BATCH * G4];
__device__ float    g_h[2][BATCH * HSZ];
__device__ ull      g_Upk[(size_t)128 * 16384];
__device__ unsigned g_cnt;

// ---------------------------------------------------------------------------
// f32x2 packed fp32 FMA (sm_100+): 2 MACs/instr.
// ---------------------------------------------------------------------------
__device__ __forceinline__ void fma2(ull& d, ull a, ull b) {
    asm("fma.rn.f32x2 %0, %1, %2, %0;" : "+l"(d) : "l"(a), "l"(b));
}
__device__ __forceinline__ ull pk2(float x, float y) {
    ull r; asm("mov.b64 %0, {%1, %2};" : "=l"(r) : "f"(x), "f"(y)); return r;
}
__device__ __forceinline__ float2 upk(ull v) {
    float2 r; asm("mov.b64 {%0, %1}, %2;" : "=f"(r.x), "=f"(r.y) : "l"(v)); return r;
}

// cp.async 16B, L1-bypass (.cg) — reads L2 directly (coherent with stcg writes).
__device__ __forceinline__ void cpa16(uint32_t saddr, const void* gptr) {
    asm volatile("cp.async.cg.shared.global [%0], [%1], 16;"
                 :: "r"(saddr), "l"(gptr) : "memory");
}
__device__ __forceinline__ void cpa_commit() {
    asm volatile("cp.async.commit_group;" ::: "memory");
}
__device__ __forceinline__ void cpa_wait1() {
    asm volatile("cp.async.wait_group 1;" ::: "memory");
}
__device__ __forceinline__ void cpa_wait0() {
    asm volatile("cp.async.wait_group 0;" ::: "memory");
}

// ---------------------------------------------------------------------------
// Init: zero h0 and barrier counter (runs every graph replay).
// ---------------------------------------------------------------------------
__global__ void lstm_init() {
    unsigned t = blockIdx.x * blockDim.x + threadIdx.x;
    if (t == 0) g_cnt = 0u;
    unsigned stride = gridDim.x * blockDim.x;
    for (unsigned i = t; i < BATCH * HSZ; i += stride) {
        g_h[0][i] = 0.f;
        g_h[1][i] = 0.f;
    }
}

// ---------------------------------------------------------------------------
// Pack U into the per-block image (see g_Upk comment). Unchanged layout.
// idx = hb*16384 + p*32 + cgrp*4 + c.
// ---------------------------------------------------------------------------
__global__ __launch_bounds__(256)
void pack_u(const float* __restrict__ u0, const float* __restrict__ u1,
            const float* __restrict__ u2, const float* __restrict__ u3)
{
    unsigned idx = blockIdx.x * 256u + threadIdx.x;     // 0 .. 2^21-1
    int c    = idx & 3;
    int cgrp = (idx >> 2) & 7;
    int p    = (idx >> 5) & 511;
    int hb   = idx >> 14;
    int gate = cgrp >> 1;
    int col  = hb * 8 + (cgrp & 1) * 4 + c;
    const float* u = (gate == 0) ? u0 : (gate == 1) ? u1 : (gate == 2) ? u2 : u3;
    g_Upk[idx] = pk2(u[(size_t)(2 * p) * HSZ + col],
                     u[(size_t)(2 * p + 1) * HSZ + col]);
}

// ---------------------------------------------------------------------------
// Phase 1: Xg = X @ [Wi|Wf|Wc|Wo] + b  (known-good; unchanged).
// ---------------------------------------------------------------------------
__global__ __launch_bounds__(256, 2)
void xg_gemm(const float* __restrict__ X,
             const float* __restrict__ w0, const float* __restrict__ w1,
             const float* __restrict__ w2, const float* __restrict__ w3,
             const float* __restrict__ bi0, const float* __restrict__ bi1,
             const float* __restrict__ bi2, const float* __restrict__ bi3)
{
    __shared__ float2 As2[16 * 128];
    __shared__ float  Bs [16 * 128];

    const int tid  = threadIdx.x;
    const int n0   = blockIdx.x * 128;
    const int m0   = blockIdx.y * 128;
    const int gate = blockIdx.x >> 3;
    const float* W  = (gate == 0) ? w0 : (gate == 1) ? w1 : (gate == 2) ? w2 : w3;
    const float* Bv = (gate == 0) ? bi0 : (gate == 1) ? bi1 : (gate == 2) ? bi2 : bi3;
    const int nloc = n0 & 1023;

    const int ar  = tid & 127;
    const int as4 = tid >> 7;
    const int mg  = m0 + ar;
    const float* Xrow = X + ((size_t)(mg & 31) * SEQ + (size_t)(mg >> 5)) * ISZ;

    const int bn4 = (tid & 31) * 4;
    const int bkr = tid >> 5;
    const int tx = tid & 15, ty = tid >> 4;

    ull acc[8][4];
    #pragma unroll
    for (int i = 0; i < 8; ++i)
        #pragma unroll
        for (int j = 0; j < 4; ++j) acc[i][j] = 0ULL;

    for (int kt = 0; kt < ISZ; kt += 16) {
        float4 a0 = *(const float4*)(Xrow + kt + as4 * 4);
        float4 a1 = *(const float4*)(Xrow + kt + (as4 + 2) * 4);
        float4 b0 = *(const float4*)(W + (size_t)(kt + bkr)     * HSZ + nloc + bn4);
        float4 b1 = *(const float4*)(W + (size_t)(kt + bkr + 8) * HSZ + nloc + bn4);

        __syncthreads();
        As2[(as4 * 4 + 0) * 128 + ar] = make_float2(a0.x, a0.x);
        As2[(as4 * 4 + 1) * 128 + ar] = make_float2(a0.y, a0.y);
        As2[(as4 * 4 + 2) * 128 + ar] = make_float2(a0.z, a0.z);
        As2[(as4 * 4 + 3) * 128 + ar] = make_float2(a0.w, a0.w);
        As2[((as4 + 2) * 4 + 0) * 128 + ar] = make_float2(a1.x, a1.x);
        As2[((as4 + 2) * 4 + 1) * 128 + ar] = make_float2(a1.y, a1.y);
        As2[((as4 + 2) * 4 + 2) * 128 + ar] = make_float2(a1.z, a1.z);
        As2[((as4 + 2) * 4 + 3) * 128 + ar] = make_float2(a1.w, a1.w);
        *(float4*)(Bs + bkr * 128 + bn4)       = b0;
        *(float4*)(Bs + (bkr + 8) * 128 + bn4) = b1;
        __syncthreads();

        #pragma unroll
        for (int k = 0; k < 16; ++k) {
            ull a[8], bb[4];
            ulonglong2 p;
            p = *(const ulonglong2*)(As2 + k * 128 + ty * 8);     a[0] = p.x; a[1] = p.y;
            p = *(const ulonglong2*)(As2 + k * 128 + ty * 8 + 2); a[2] = p.x; a[3] = p.y;
            p = *(const ulonglong2*)(As2 + k * 128 + ty * 8 + 4); a[4] = p.x; a[5] = p.y;
            p = *(const ulonglong2*)(As2 + k * 128 + ty * 8 + 6); a[6] = p.x; a[7] = p.y;
            p = *(const ulonglong2*)(Bs + k * 128 + tx * 8);      bb[0] = p.x; bb[1] = p.y;
            p = *(const ulonglong2*)(Bs + k * 128 + tx * 8 + 4);  bb[2] = p.x; bb[3] = p.y;
            #pragma unroll
            for (int i = 0; i < 8; ++i)
                #pragma unroll
                for (int j = 0; j < 4; ++j) fma2(acc[i][j], a[i], bb[j]);
        }
    }

    float4 bb0 = *(const float4*)(Bv + nloc + tx * 8);
    float4 bb1 = *(const float4*)(Bv + nloc + tx * 8 + 4);
    #pragma unroll
    for (int i = 0; i < 8; ++i) {
        float2 c0 = upk(acc[i][0]), c1 = upk(acc[i][1]);
        float2 c2 = upk(acc[i][2]), c3 = upk(acc[i][3]);
        float4 o0 = make_float4(c0.x + bb0.x, c0.y + bb0.y, c1.x + bb0.z, c1.y + bb0.w);
        float4 o1 = make_float4(c2.x + bb1.x, c2.y + bb1.y, c3.x + bb1.z, c3.y + bb1.w);
        size_t row = (size_t)(m0 + ty * 8 + i) * G4 + n0 + tx * 8;
        *(float4*)(g_Xg + row)     = o0;
        *(float4*)(g_Xg + row + 4) = o1;
    }
}

// ---------------------------------------------------------------------------
// Phase 2: persistent recurrence — 4b x 8c retile, split-K 8, one warp per
// k-range, barrier-free chunk pipeline.
// Thread (ks = tid>>5, lane = tid&31): bg = lane&7 (batches bg*4..+3),
// cg2 = lane>>3 (cols: cgrp cg2 and cgrp cg2+4 -> conflict-free U LDS).
// U (128KB) smem-resident. h: per warp 16KB k-range in four 4KB cp.async
// chunks, 2 buffers; WAR closed by program distance (stage issued ~600 instr
// after buffer's last LDS, and cp.async must read L2 (~250cyc) first).
// Rs (32KB) ALIASES the Hbuf region (dead at reduce time; __syncthreads
// separates). Rs/Gs layout [col][b] for packed float4 access.
// smem: Us 128KB + Hbuf/Rs 64KB + Gs 4KB + XgS 8KB = 204KB.
// ---------------------------------------------------------------------------
#define SMEM_P2 ((32768 + 16384 + 1024 + 2048) * 4)

// Stage chunk cidx of this warp's k-range into buffer buf (4KB, 8 cpa16/thr).
// id = i*32+lane: b = id>>3 (4 batch-rows/instr, 128B contiguous each).
#define STAGE_CHUNK(buf, cidx) do {                                           \
    const float* hs_ = g_h[cur] + ks * 128 + (cidx) * 32;                     \
    uint32_t db_ = HbA + (uint32_t)(((ks * 2 + (buf)) * 1024) * 4);           \
    _Pragma("unroll")                                                         \
    for (int i_ = 0; i_ < 8; ++i_) {                                          \
        int id_ = i_ * 32 + lane;                                             \
        int b_  = id_ >> 3;                                                   \
        int g_  = id_ & 7;                                                    \
        int sl_ = g_ ^ (b_ >> 2);                                             \
        cpa16(db_ + (uint32_t)((b_ * 32 + sl_ * 4) * 4),                      \
              hs_ + (size_t)b_ * 1024 + g_ * 4);                              \
    }                                                                         \
} while (0)

// Compute chunk cidx (32 k) from buffer buf. 8 granules x (12 LDS + 64 fma2).
#define COMPUTE_CHUNK(buf, cidx) do {                                         \
    const float* hbuf_ = Hb + (ks * 2 + (buf)) * 1024;                        \
    const ull* up0_ = Us + (size_t)(ks * 64 + (cidx) * 16) * 32;              \
    _Pragma("unroll")                                                         \
    for (int g_ = 0; g_ < 8; ++g_) {                                          \
        const ull* up_ = up0_ + g_ * 64;                                      \
        ulonglong2 uA0 = *(const ulonglong2*)(up_ + cg2 * 4);                 \
        ulonglong2 uA1 = *(const ulonglong2*)(up_ + cg2 * 4 + 2);             \
        ulonglong2 uB0 = *(const ulonglong2*)(up_ + (cg2 + 4) * 4);           \
        ulonglong2 uB1 = *(const ulonglong2*)(up_ + (cg2 + 4) * 4 + 2);       \
        ulonglong2 vA0 = *(const ulonglong2*)(up_ + 32 + cg2 * 4);            \
        ulonglong2 vA1 = *(const ulonglong2*)(up_ + 32 + cg2 * 4 + 2);        \
        ulonglong2 vB0 = *(const ulonglong2*)(up_ + 32 + (cg2 + 4) * 4);      \
        ulonglong2 vB1 = *(const ulonglong2*)(up_ + 32 + (cg2 + 4) * 4 + 2);  \
        const float* hp_ = hbuf_ + bg * 128 + ((g_ ^ bg) * 4);                \
        _Pragma("unroll")                                                     \
        for (int lb_ = 0; lb_ < 4; ++lb_) {                                   \
            ulonglong2 h_ = *(const ulonglong2*)(hp_ + lb_ * 32);             \
            fma2(accA[lb_][0], h_.x, uA0.x); fma2(accA[lb_][1], h_.x, uA0.y); \
            fma2(accA[lb_][2], h_.x, uA1.x); fma2(accA[lb_][3], h_.x, uA1.y); \
            fma2(accB[lb_][0], h_.x, uB0.x); fma2(accB[lb_][1], h_.x, uB0.y); \
            fma2(accB[lb_][2], h_.x, uB1.x); fma2(accB[lb_][3], h_.x, uB1.y); \
            fma2(accA[lb_][0], h_.y, vA0.x); fma2(accA[lb_][1], h_.y, vA0.y); \
            fma2(accA[lb_][2], h_.y, vA1.x); fma2(accA[lb_][3], h_.y, vA1.y); \
            fma2(accB[lb_][0], h_.y, vB0.x); fma2(accB[lb_][1], h_.y, vB0.y); \
            fma2(accB[lb_][2], h_.y, vB1.x); fma2(accB[lb_][3], h_.y, vB1.y); \
        }                                                                     \
    }                                                                         \
} while (0)

__global__ __launch_bounds__(NT2, 1)
void lstm_rec(float* __restrict__ out)
{
    extern __shared__ float sm[];
    ull*   Us  = (ull*)sm;                   // 16384 ull = 128KB
    float* Hb  = sm + 32768;                 // Hbuf 64KB (8 groups x 2 x 4KB)
    float* Rs  = sm + 32768;                 // 32KB, ALIASES Hb (see header)
    float* Gs  = sm + 32768 + 16384;         // [col][b], 4KB
    float* XgS = Gs + 1024;                  // 2 x [b][32], 8KB

    const int tid  = threadIdx.x;
    const int hb   = blockIdx.x;
    const int ks   = tid >> 5;               // 0..7, k-range 128
    const int lane = tid & 31;
    const int bg   = lane & 7;               // batches bg*4..+3
    const int cg2  = lane >> 3;              // cgrps {cg2, cg2+4}

    // epilogue role
    const int ub = tid >> 3;
    const int j  = tid & 7;
    const int kglob = hb * 8 + j;
    float creg = 0.f;

    // Xg staging role (XgS layout [b][32cols], col = xq*4..+3)
    const int xb = tid >> 3, xq = tid & 7;
    const size_t xgcol = (size_t)(xq >> 1) * 1024 + hb * 8 + (xq & 1) * 4;

    const uint32_t HbA = (uint32_t)__cvta_generic_to_shared(Hb);
    const uint32_t XgA = (uint32_t)__cvta_generic_to_shared(XgS);

    float* out_h = out + (size_t)BATCH * SEQ * HSZ;
    float* out_c = out_h + BATCH * HSZ;

    // --- one-time: load this block's U slice (128KB) into smem ---
    {
        const float4* src = (const float4*)(g_Upk + (size_t)hb * 16384);
        float4* dst = (float4*)Us;
        #pragma unroll 8
        for (int i = tid; i < 8192; i += NT2) dst[i] = src[i];
    }
    __syncthreads();

    int cur = 0;
    for (int s = 0; s < SEQ; ++s) {
        // stage chunks 0,1 (grid barrier at prev step end => g_h[cur] valid;
        // Hb region free: prior reduce finished before that barrier)
        STAGE_CHUNK(0, 0);
        if (s == 0)
            cpa16(XgA + (uint32_t)((xb * 32 + xq * 4) * 4),
                  g_Xg + (size_t)xb * G4 + xgcol);
        cpa_commit();                                   // G1 = c0 (+X0 once)
        STAGE_CHUNK(1, 1); cpa_commit();                // G2 = c1

        ull accA[4][4], accB[4][4];
        #pragma unroll
        for (int a_ = 0; a_ < 4; ++a_)
            #pragma unroll
            for (int b_ = 0; b_ < 4; ++b_) { accA[a_][b_] = 0ULL; accB[a_][b_] = 0ULL; }

        cpa_wait1();                                    // c0 ready
        COMPUTE_CHUNK(0, 0);
        STAGE_CHUNK(0, 2);
        {
            int sn = (s + 1 < SEQ) ? s + 1 : SEQ - 1;   // next-step Xg
            cpa16(XgA + (uint32_t)((((s + 1) & 1) * 1024 + xb * 32 + xq * 4) * 4),
                  g_Xg + ((size_t)sn * BATCH + xb) * G4 + xgcol);
        }
        cpa_commit();                                   // G3 = c2 + X_{s+1}

        cpa_wait1();                                    // c1 ready
        COMPUTE_CHUNK(1, 1);
        STAGE_CHUNK(1, 3); cpa_commit();                // G4 = c3

        cpa_wait1();                                    // c2 (+Xg) ready
        COMPUTE_CHUNK(0, 2);

        cpa_wait0();                                    // c3 ready
        COMPUTE_CHUNK(1, 3);

        // all warps done computing before Rs (aliases Hb) is written
        __syncthreads();

        // --- write split-K partials, layout [ks][col][b] ---
        {
            float* r = Rs + ks * 1024;
            #pragma unroll
            for (int c = 0; c < 4; ++c) {
                float2 t; float4 wA, wB;
                t = upk(accA[0][c]); wA.x = t.x + t.y;
                t = upk(accA[1][c]); wA.y = t.x + t.y;
                t = upk(accA[2][c]); wA.z = t.x + t.y;
                t = upk(accA[3][c]); wA.w = t.x + t.y;
                t = upk(accB[0][c]); wB.x = t.x + t.y;
                t = upk(accB[1][c]); wB.y = t.x + t.y;
                t = upk(accB[2][c]); wB.z = t.x + t.y;
                t = upk(accB[3][c]); wB.w = t.x + t.y;
                *(float4*)(r + (cg2 * 4 + c) * 32 + bg * 4)        = wA;
                *(float4*)(r + (16 + cg2 * 4 + c) * 32 + bg * 4)   = wB;
            }
        }
        __syncthreads();

        // --- reduce 8 partials + add Xg -> Gs[col][b] ---
        {
            int o = tid * 4;                 // o = col*32 + b
            float4 v = make_float4(0.f, 0.f, 0.f, 0.f);
            #pragma unroll
            for (int k2 = 0; k2 < 8; ++k2) {
                float4 p = *(const float4*)(Rs + k2 * 1024 + o);
                v.x += p.x; v.y += p.y; v.z += p.z; v.w += p.w;
            }
            int colr = tid >> 3, br = (tid & 7) * 4;
            const float* Xc = XgS + (s & 1) * 1024;
            v.x += Xc[(br + 0) * 32 + colr];
            v.y += Xc[(br + 1) * 32 + colr];
            v.z += Xc[(br + 2) * 32 + colr];
            v.w += Xc[(br + 3) * 32 + colr];
            *(float4*)(Gs + o) = v;
        }
        __syncthreads();

        // --- gates + state update (role: ub, j); Gs is [col][b] ---
        {
            float gi = Gs[(j)      * 32 + ub];
            float gf = Gs[(8 + j)  * 32 + ub];
            float gc = Gs[(16 + j) * 32 + ub];
            float go = Gs[(24 + j) * 32 + ub];
            float it = 1.f / (1.f + __expf(-gi));
            float ft = 1.f / (1.f + __expf(-gf));
            float ct = tanhf(gc);
            float ot = 1.f / (1.f + __expf(-go));
            creg = ft * creg + it * ct;
            float hn = ot * tanhf(creg);
            __stcg(&g_h[cur ^ 1][ub * HSZ + kglob], hn);
            out[((size_t)ub * SEQ + s) * HSZ + kglob] = hn;
            if (s == SEQ - 1) {
                out_h[ub * HSZ + kglob] = hn;
                out_c[ub * HSZ + kglob] = creg;
            }
        }

        // --- grid barrier: release-add + acquire-spin ---
        __syncthreads();
        if (tid == 0) {
            unsigned old;
            asm volatile("atom.add.release.gpu.u32 %0, [%1], 1;"
                         : "=r"(old) : "l"(&g_cnt) : "memory");
            unsigned target = (unsigned)NB2 * (unsigned)(s + 1);
            unsigned v;
            do {
                asm volatile("ld.acquire.gpu.u32 %0, [%1];"
                             : "=r"(v) : "l"(&g_cnt) : "memory");
            } while (v < target);
        }
        __syncthreads();
        cur ^= 1;
    }
}

// ---------------------------------------------------------------------------
// Launch. Inputs: X, w_i,u_i,b_i, w_f,u_f,b_f, w_c,u_c,b_c, w_o,u_o,b_o.
// Output: [hidden_seq (B,S,H) | h_T (B,H) | c_T (B,H)] fp32.
// ---------------------------------------------------------------------------
extern "C" void kernel_launch(void* const* d_in, const int* in_sizes, int n_in,
                              void* d_out, int out_size) {
    (void)in_sizes; (void)n_in; (void)out_size;
    const float* X   = (const float*)d_in[0];
    const float* w_i = (const float*)d_in[1];
    const float* u_i = (const float*)d_in[2];
    const float* b_i = (const float*)d_in[3];
    const float* w_f = (const float*)d_in[4];
    const float* u_f = (const float*)d_in[5];
    const float* b_f = (const float*)d_in[6];
    const float* w_c = (const float*)d_in[7];
    const float* u_c = (const float*)d_in[8];
    const float* b_c = (const float*)d_in[9];
    const float* w_o = (const float*)d_in[10];
    const float* u_o = (const float*)d_in[11];
    const float* b_o = (const float*)d_in[12];
    float* out = (float*)d_out;

    lstm_init<<<64, 256>>>();
    pack_u<<<8192, 256>>>(u_i, u_f, u_c, u_o);

    dim3 g1(32, 128);   // N/128 x M/128
    xg_gemm<<<g1, 256>>>(X, w_i, w_f, w_c, w_o, b_i, b_f, b_c, b_o);

    cudaFuncSetAttribute(lstm_rec, cudaFuncAttributeMaxDynamicSharedMemorySize,
                         SMEM_P2);
    lstm_rec<<<NB2, NT2, SMEM_P2>>>(out);
}

// round 13
// speedup vs baseline: 1.3485x; 1.3485x over previous
#include <cuda_runtime.h>
#include <cuda_bf16.h>
#include <cstdint>
#include <cstddef>

#define BATCH 32
#define SEQ   512
#define ISZ   512
#define HSZ   1024
#define G4    4096
#define NB2   128
#define NT2   512

typedef unsigned long long ull;

// ---------------------------------------------------------------------------
// Device scratch (allocation-free rule: __device__ globals).
// g_Xg : [s][b][4096] input projections + bias, fp32, 256MB.
// g_h  : ping-pong hidden state, natural [b][k] layout.
// g_Upk: per-block image of packed U: [hb][p(512)][cgrp(8)][c(4)] ull,
//        ull = {U[2p][col], U[2p+1][col]}, col = hb*8+(cgrp&1)*4+c,
//        gate = cgrp>>1. 16MB. Block hb copies its contiguous 128KB once.
// ---------------------------------------------------------------------------
__device__ float    g_Xg[(size_t)SEQ * BATCH * G4];
__device__ float    g_h[2][BATCH * HSZ];
__device__ ull      g_Upk[(size_t)128 * 16384];
__device__ unsigned g_cnt;

// ---------------------------------------------------------------------------
// f32x2 packed fp32 FMA (sm_100+): 2 MACs/instr.
// ---------------------------------------------------------------------------
__device__ __forceinline__ void fma2(ull& d, ull a, ull b) {
    asm("fma.rn.f32x2 %0, %1, %2, %0;" : "+l"(d) : "l"(a), "l"(b));
}
__device__ __forceinline__ ull pk2(float x, float y) {
    ull r; asm("mov.b64 %0, {%1, %2};" : "=l"(r) : "f"(x), "f"(y)); return r;
}
__device__ __forceinline__ float2 upk(ull v) {
    float2 r; asm("mov.b64 {%0, %1}, %2;" : "=f"(r.x), "=f"(r.y) : "l"(v)); return r;
}

// cp.async 16B, L1-bypass (.cg) — reads L2 directly (coherent with stcg writes).
__device__ __forceinline__ void cpa16(uint32_t saddr, const void* gptr) {
    asm volatile("cp.async.cg.shared.global [%0], [%1], 16;"
                 :: "r"(saddr), "l"(gptr) : "memory");
}
__device__ __forceinline__ void cpa_commit() {
    asm volatile("cp.async.commit_group;" ::: "memory");
}
__device__ __forceinline__ void cpa_wait1() {
    asm volatile("cp.async.wait_group 1;" ::: "memory");
}
__device__ __forceinline__ void cpa_wait0() {
    asm volatile("cp.async.wait_group 0;" ::: "memory");
}

// ---------------------------------------------------------------------------
// Init: zero h0 and barrier counter (runs every graph replay).
// ---------------------------------------------------------------------------
__global__ void lstm_init() {
    unsigned t = blockIdx.x * blockDim.x + threadIdx.x;
    if (t == 0) g_cnt = 0u;
    unsigned stride = gridDim.x * blockDim.x;
    for (unsigned i = t; i < BATCH * HSZ; i += stride) {
        g_h[0][i] = 0.f;
        g_h[1][i] = 0.f;
    }
}

// ---------------------------------------------------------------------------
// Pack U into the per-block image (see g_Upk comment).
// idx = hb*16384 + p*32 + cgrp*4 + c.
// ---------------------------------------------------------------------------
__global__ __launch_bounds__(256)
void pack_u(const float* __restrict__ u0, const float* __restrict__ u1,
            const float* __restrict__ u2, const float* __restrict__ u3)
{
    unsigned idx = blockIdx.x * 256u + threadIdx.x;     // 0 .. 2^21-1
    int c    = idx & 3;
    int cgrp = (idx >> 2) & 7;
    int p    = (idx >> 5) & 511;
    int hb   = idx >> 14;
    int gate = cgrp >> 1;
    int col  = hb * 8 + (cgrp & 1) * 4 + c;
    const float* u = (gate == 0) ? u0 : (gate == 1) ? u1 : (gate == 2) ? u2 : u3;
    g_Upk[idx] = pk2(u[(size_t)(2 * p) * HSZ + col],
                     u[(size_t)(2 * p + 1) * HSZ + col]);
}

// ---------------------------------------------------------------------------
// Phase 1: Xg = X @ [Wi|Wf|Wc|Wo] + b  (known-good; unchanged).
// ---------------------------------------------------------------------------
__global__ __launch_bounds__(256, 2)
void xg_gemm(const float* __restrict__ X,
             const float* __restrict__ w0, const float* __restrict__ w1,
             const float* __restrict__ w2, const float* __restrict__ w3,
             const float* __restrict__ bi0, const float* __restrict__ bi1,
             const float* __restrict__ bi2, const float* __restrict__ bi3)
{
    __shared__ float2 As2[16 * 128];
    __shared__ float  Bs [16 * 128];

    const int tid  = threadIdx.x;
    const int n0   = blockIdx.x * 128;
    const int m0   = blockIdx.y * 128;
    const int gate = blockIdx.x >> 3;
    const float* W  = (gate == 0) ? w0 : (gate == 1) ? w1 : (gate == 2) ? w2 : w3;
    const float* Bv = (gate == 0) ? bi0 : (gate == 1) ? bi1 : (gate == 2) ? bi2 : bi3;
    const int nloc = n0 & 1023;

    const int ar  = tid & 127;
    const int as4 = tid >> 7;
    const int mg  = m0 + ar;
    const float* Xrow = X + ((size_t)(mg & 31) * SEQ + (size_t)(mg >> 5)) * ISZ;

    const int bn4 = (tid & 31) * 4;
    const int bkr = tid >> 5;
    const int tx = tid & 15, ty = tid >> 4;

    ull acc[8][4];
    #pragma unroll
    for (int i = 0; i < 8; ++i)
        #pragma unroll
        for (int j = 0; j < 4; ++j) acc[i][j] = 0ULL;

    for (int kt = 0; kt < ISZ; kt += 16) {
        float4 a0 = *(const float4*)(Xrow + kt + as4 * 4);
        float4 a1 = *(const float4*)(Xrow + kt + (as4 + 2) * 4);
        float4 b0 = *(const float4*)(W + (size_t)(kt + bkr)     * HSZ + nloc + bn4);
        float4 b1 = *(const float4*)(W + (size_t)(kt + bkr + 8) * HSZ + nloc + bn4);

        __syncthreads();
        As2[(as4 * 4 + 0) * 128 + ar] = make_float2(a0.x, a0.x);
        As2[(as4 * 4 + 1) * 128 + ar] = make_float2(a0.y, a0.y);
        As2[(as4 * 4 + 2) * 128 + ar] = make_float2(a0.z, a0.z);
        As2[(as4 * 4 + 3) * 128 + ar] = make_float2(a0.w, a0.w);
        As2[((as4 + 2) * 4 + 0) * 128 + ar] = make_float2(a1.x, a1.x);
        As2[((as4 + 2) * 4 + 1) * 128 + ar] = make_float2(a1.y, a1.y);
        As2[((as4 + 2) * 4 + 2) * 128 + ar] = make_float2(a1.z, a1.z);
        As2[((as4 + 2) * 4 + 3) * 128 + ar] = make_float2(a1.w, a1.w);
        *(float4*)(Bs + bkr * 128 + bn4)       = b0;
        *(float4*)(Bs + (bkr + 8) * 128 + bn4) = b1;
        __syncthreads();

        #pragma unroll
        for (int k = 0; k < 16; ++k) {
            ull a[8], bb[4];
            ulonglong2 p;
            p = *(const ulonglong2*)(As2 + k * 128 + ty * 8);     a[0] = p.x; a[1] = p.y;
            p = *(const ulonglong2*)(As2 + k * 128 + ty * 8 + 2); a[2] = p.x; a[3] = p.y;
            p = *(const ulonglong2*)(As2 + k * 128 + ty * 8 + 4); a[4] = p.x; a[5] = p.y;
            p = *(const ulonglong2*)(As2 + k * 128 + ty * 8 + 6); a[6] = p.x; a[7] = p.y;
            p = *(const ulonglong2*)(Bs + k * 128 + tx * 8);      bb[0] = p.x; bb[1] = p.y;
            p = *(const ulonglong2*)(Bs + k * 128 + tx * 8 + 4);  bb[2] = p.x; bb[3] = p.y;
            #pragma unroll
            for (int i = 0; i < 8; ++i)
                #pragma unroll
                for (int j = 0; j < 4; ++j) fma2(acc[i][j], a[i], bb[j]);
        }
    }

    float4 bb0 = *(const float4*)(Bv + nloc + tx * 8);
    float4 bb1 = *(const float4*)(Bv + nloc + tx * 8 + 4);
    #pragma unroll
    for (int i = 0; i < 8; ++i) {
        float2 c0 = upk(acc[i][0]), c1 = upk(acc[i][1]);
        float2 c2 = upk(acc[i][2]), c3 = upk(acc[i][3]);
        float4 o0 = make_float4(c0.x + bb0.x, c0.y + bb0.y, c1.x + bb0.z, c1.y + bb0.w);
        float4 o1 = make_float4(c2.x + bb1.x, c2.y + bb1.y, c3.x + bb1.z, c3.y + bb1.w);
        size_t row = (size_t)(m0 + ty * 8 + i) * G4 + n0 + tx * 8;
        *(float4*)(g_Xg + row)     = o0;
        *(float4*)(g_Xg + row + 4) = o1;
    }
}

// ---------------------------------------------------------------------------
// Phase 2: persistent recurrence — R11 pipeline at 512 threads (16 warps).
// 8 warp-pair groups (ksp = tid>>6, 64 threads), split-K 8, k-range 128 each.
// Per group: four 4KB h chunks through 2 smem buffers; PAIR_BAR closes the
// WAR window after each compute before the buffer is restaged (R11-proven).
// Microkernel identical to R11: 4 batches x 4 cols, k-paired f32x2.
// Rs (32KB) aliases Hbuf (dead at reduce; __syncthreads separates).
// smem: Us 128KB + Hbuf/Rs 64KB + Gs 4KB + XgS 8KB = 204KB.
// ---------------------------------------------------------------------------
#define SMEM_P2 ((32768 + 16384 + 1024 + 2048) * 4)

// Stage chunk cidx (32 k) of this group's k-range into buffer buf.
// 64 threads x 4 cpa16: id = i*64+t64 -> b = id>>3, g = id&7 (k-granule).
// Lanes k-contiguous within batch rows (4 x 32B runs per instr).
#define STAGE_CHUNK(buf, cidx) do {                                           \
    const float* hs_ = g_h[cur] + ksp * 128 + (cidx) * 32;                    \
    uint32_t db_ = HbA + (uint32_t)(((ksp * 2 + (buf)) * 1024) * 4);          \
    _Pragma("unroll")                                                         \
    for (int i_ = 0; i_ < 4; ++i_) {                                          \
        int id_ = i_ * 64 + t64;                                              \
        int b_  = id_ >> 3;                                                   \
        int g_  = id_ & 7;                                                    \
        int sl_ = g_ ^ (b_ >> 2);                                             \
        cpa16(db_ + (uint32_t)((b_ * 32 + sl_ * 4) * 4),                      \
              hs_ + (size_t)b_ * 1024 + g_ * 4);                              \
    }                                                                         \
} while (0)

// Compute chunk cidx (32 k = 8 granules of 2 k-pairs) from buffer buf.
// Per granule: 4 U LDS.128 + 4 h LDS.128 + 32 fma2 (all conflict-free).
#define COMPUTE_CHUNK(buf, cidx) do {                                         \
    const float* hb_ = Hb + (ksp * 2 + (buf)) * 1024 + bg * 128;              \
    const ull*   ur_ = Us + (size_t)(ksp * 64 + (cidx) * 16) * 32 + cgrp * 4; \
    _Pragma("unroll")                                                         \
    for (int g_ = 0; g_ < 8; ++g_) {                                          \
        const ulonglong2* u0_ = (const ulonglong2*)(ur_ + (size_t)g_ * 64);   \
        const ulonglong2* u1_ = (const ulonglong2*)(ur_ + (size_t)g_ * 64 + 32);\
        ulonglong2 u00 = u0_[0], u01 = u0_[1];                                \
        ulonglong2 u10 = u1_[0], u11 = u1_[1];                                \
        int so_ = (g_ ^ bg) * 4;                                              \
        ulonglong2 h0 = *(const ulonglong2*)(hb_ + so_);                      \
        ulonglong2 h1 = *(const ulonglong2*)(hb_ + 32 + so_);                 \
        ulonglong2 h2 = *(const ulonglong2*)(hb_ + 64 + so_);                 \
        ulonglong2 h3 = *(const ulonglong2*)(hb_ + 96 + so_);                 \
        fma2(a00, h0.x, u00.x); fma2(a01, h0.x, u00.y);                       \
        fma2(a02, h0.x, u01.x); fma2(a03, h0.x, u01.y);                       \
        fma2(a10, h1.x, u00.x); fma2(a11, h1.x, u00.y);                       \
        fma2(a12, h1.x, u01.x); fma2(a13, h1.x, u01.y);                       \
        fma2(a20, h2.x, u00.x); fma2(a21, h2.x, u00.y);                       \
        fma2(a22, h2.x, u01.x); fma2(a23, h2.x, u01.y);                       \
        fma2(a30, h3.x, u00.x); fma2(a31, h3.x, u00.y);                       \
        fma2(a32, h3.x, u01.x); fma2(a33, h3.x, u01.y);                       \
        fma2(a00, h0.y, u10.x); fma2(a01, h0.y, u10.y);                       \
        fma2(a02, h0.y, u11.x); fma2(a03, h0.y, u11.y);                       \
        fma2(a10, h1.y, u10.x); fma2(a11, h1.y, u10.y);                       \
        fma2(a12, h1.y, u11.x); fma2(a13, h1.y, u11.y);                       \
        fma2(a20, h2.y, u10.x); fma2(a21, h2.y, u10.y);                       \
        fma2(a22, h2.y, u11.x); fma2(a23, h2.y, u11.y);                       \
        fma2(a30, h3.y, u10.x); fma2(a31, h3.y, u10.y);                       \
        fma2(a32, h3.y, u11.x); fma2(a33, h3.y, u11.y);                       \
    }                                                                         \
} while (0)

#define PAIR_BAR() asm volatile("bar.sync %0, 64;" :: "r"(1 + ksp) : "memory")

__global__ __launch_bounds__(NT2, 1)
void lstm_rec(float* __restrict__ out)
{
    extern __shared__ float sm[];
    ull*   Us  = (ull*)sm;                   // 16384 ull = 128KB
    float* Hb  = sm + 32768;                 // Hbuf 64KB (8 groups x 2 x 4KB)
    float* Rs  = sm + 32768;                 // 32KB, ALIASES Hb
    float* Gs  = sm + 32768 + 16384;         // [b][32] gate pre-activations
    float* XgS = Gs + 1024;                  // 2 x [b][32]

    const int tid  = threadIdx.x;
    const int hb   = blockIdx.x;
    const int ksp  = tid >> 6;               // 0..7, k-range 128
    const int t64  = tid & 63;
    const int og   = t64;
    const int bg   = og & 7;                 // batches bg*4..+3
    const int cgrp = og >> 3;                // cols cgrp*4..+3 (of 32)

    // epilogue roles (first 256 threads only)
    const int ub = (tid & 255) >> 3;
    const int j  = tid & 7;
    const int kglob = hb * 8 + j;
    float creg = 0.f;

    // Xg staging role (first 256 threads)
    const int xb = (tid & 255) >> 3, xq = tid & 7;
    const size_t xgcol = (size_t)(xq >> 1) * 1024 + hb * 8 + (xq & 1) * 4;

    const uint32_t HbA = (uint32_t)__cvta_generic_to_shared(Hb);
    const uint32_t XgA = (uint32_t)__cvta_generic_to_shared(XgS);

    float* out_h = out + (size_t)BATCH * SEQ * HSZ;
    float* out_c = out_h + BATCH * HSZ;

    // --- one-time: load this block's U slice (128KB) into smem ---
    {
        const float4* src = (const float4*)(g_Upk + (size_t)hb * 16384);
        float4* dst = (float4*)Us;
        #pragma unroll 4
        for (int i = tid; i < 8192; i += NT2) dst[i] = src[i];
    }
    __syncthreads();

    int cur = 0;
    for (int s = 0; s < SEQ; ++s) {
        // stage chunks 0,1 (grid barrier at prev step end => g_h[cur] valid;
        // Hb region free: prior reduce finished before that barrier)
        STAGE_CHUNK(0, 0);
        if (s == 0 && tid < 256)
            cpa16(XgA + (uint32_t)((xb * 32 + xq * 4) * 4),
                  g_Xg + (size_t)xb * G4 + xgcol);
        cpa_commit();                                   // G1 = c0 (+X0 once)
        STAGE_CHUNK(1, 1); cpa_commit();                // G2 = c1

        ull a00 = 0, a01 = 0, a02 = 0, a03 = 0;
        ull a10 = 0, a11 = 0, a12 = 0, a13 = 0;
        ull a20 = 0, a21 = 0, a22 = 0, a23 = 0;
        ull a30 = 0, a31 = 0, a32 = 0, a33 = 0;

        // c=0: wait G1, compute buf0, close WAR, restage c2 (+ next Xg) -> G3
        cpa_wait1(); PAIR_BAR();
        COMPUTE_CHUNK(0, 0);
        PAIR_BAR();
        STAGE_CHUNK(0, 2);
        {
            int sn = (s + 1 < SEQ) ? s + 1 : SEQ - 1;
            if (tid < 256)
                cpa16(XgA + (uint32_t)((((s + 1) & 1) * 1024 + xb * 32 + xq * 4) * 4),
                      g_Xg + ((size_t)sn * BATCH + xb) * G4 + xgcol);
        }
        cpa_commit();                                   // G3 = c2 + X_{s+1}

        // c=1: wait G2, compute buf1, close WAR, restage c3             -> G4
        cpa_wait1(); PAIR_BAR();
        COMPUTE_CHUNK(1, 1);
        PAIR_BAR();
        STAGE_CHUNK(1, 3); cpa_commit();                // G4 = c3

        // c=2: wait G3 (c2 + Xg), compute buf0
        cpa_wait1(); PAIR_BAR();
        COMPUTE_CHUNK(0, 2);

        // c=3: wait G4, compute buf1
        cpa_wait0(); PAIR_BAR();
        COMPUTE_CHUNK(1, 3);

        // all groups done computing before Rs (aliases Hb) is written
        __syncthreads();

        // --- write split-K partials: r[lb*4 + c] per thread ---
        {
            float* r = Rs + ksp * 1024 + og * 16;
            float2 t;
            t = upk(a00); r[0]  = t.x + t.y;  t = upk(a01); r[1]  = t.x + t.y;
            t = upk(a02); r[2]  = t.x + t.y;  t = upk(a03); r[3]  = t.x + t.y;
            t = upk(a10); r[4]  = t.x + t.y;  t = upk(a11); r[5]  = t.x + t.y;
            t = upk(a12); r[6]  = t.x + t.y;  t = upk(a13); r[7]  = t.x + t.y;
            t = upk(a20); r[8]  = t.x + t.y;  t = upk(a21); r[9]  = t.x + t.y;
            t = upk(a22); r[10] = t.x + t.y;  t = upk(a23); r[11] = t.x + t.y;
            t = upk(a30); r[12] = t.x + t.y;  t = upk(a31); r[13] = t.x + t.y;
            t = upk(a32); r[14] = t.x + t.y;  t = upk(a33); r[15] = t.x + t.y;
        }
        __syncthreads();

        // --- reduce 8 partials + add Xg (smem) -> Gs[b][c]  (tid<256) ---
        if (tid < 256) {
            #pragma unroll
            for (int i = 0; i < 4; ++i) {
                int o   = tid * 4 + i;
                int oog = o >> 4, li = o & 15;
                int bb  = (oog & 7) * 4 + (li >> 2);
                int cc  = (oog >> 3) * 4 + (li & 3);
                float v = Rs[o]        + Rs[1024 + o] + Rs[2048 + o] + Rs[3072 + o]
                        + Rs[4096 + o] + Rs[5120 + o] + Rs[6144 + o] + Rs[7168 + o];
                v += XgS[(s & 1) * 1024 + bb * 32 + cc];
                Gs[bb * 32 + cc] = v;
            }
        }
        __syncthreads();

        // --- gates + state update (tid<256; role: ub, j) ---
        if (tid < 256) {
            float gi = Gs[ub * 32 + j];
            float gf = Gs[ub * 32 + 8 + j];
            float gc = Gs[ub * 32 + 16 + j];
            float go = Gs[ub * 32 + 24 + j];
            float it = 1.f / (1.f + __expf(-gi));
            float ft = 1.f / (1.f + __expf(-gf));
            float ct = tanhf(gc);
            float ot = 1.f / (1.f + __expf(-go));
            creg = ft * creg + it * ct;
            float hn = ot * tanhf(creg);
            __stcg(&g_h[cur ^ 1][ub * HSZ + kglob], hn);
            out[((size_t)ub * SEQ + s) * HSZ + kglob] = hn;
            if (s == SEQ - 1) {
                out_h[ub * HSZ + kglob] = hn;
                out_c[ub * HSZ + kglob] = creg;
            }
        }

        // --- grid barrier: release-add + acquire-spin ---
        __syncthreads();
        if (tid == 0) {
            unsigned old;
            asm volatile("atom.add.release.gpu.u32 %0, [%1], 1;"
                         : "=r"(old) : "l"(&g_cnt) : "memory");
            unsigned target = (unsigned)NB2 * (unsigned)(s + 1);
            unsigned v;
            do {
                asm volatile("ld.acquire.gpu.u32 %0, [%1];"
                             : "=r"(v) : "l"(&g_cnt) : "memory");
            } while (v < target);
        }
        __syncthreads();
        cur ^= 1;
    }
}

// ---------------------------------------------------------------------------
// Launch. Inputs: X, w_i,u_i,b_i, w_f,u_f,b_f, w_c,u_c,b_c, w_o,u_o,b_o.
// Output: [hidden_seq (B,S,H) | h_T (B,H) | c_T (B,H)] fp32.
// ---------------------------------------------------------------------------
extern "C" void kernel_launch(void* const* d_in, const int* in_sizes, int n_in,
                              void* d_out, int out_size) {
    (void)in_sizes; (void)n_in; (void)out_size;
    const float* X   = (const float*)d_in[0];
    const float* w_i = (const float*)d_in[1];
    const float* u_i = (const float*)d_in[2];
    const float* b_i = (const float*)d_in[3];
    const float* w_f = (const float*)d_in[4];
    const float* u_f = (const float*)d_in[5];
    const float* b_f = (const float*)d_in[6];
    const float* w_c = (const float*)d_in[7];
    const float* u_c = (const float*)d_in[8];
    const float* b_c = (const float*)d_in[9];
    const float* w_o = (const float*)d_in[10];
    const float* u_o = (const float*)d_in[11];
    const float* b_o = (const float*)d_in[12];
    float* out = (float*)d_out;

    lstm_init<<<64, 256>>>();
    pack_u<<<8192, 256>>>(u_i, u_f, u_c, u_o);

    dim3 g1(32, 128);   // N/128 x M/128
    xg_gemm<<<g1, 256>>>(X, w_i, w_f, w_c, w_o, b_i, b_f, b_c, b_o);

    cudaFuncSetAttribute(lstm_rec, cudaFuncAttributeMaxDynamicSharedMemorySize,
                         SMEM_P2);
    lstm_rec<<<NB2, NT2, SMEM_P2>>>(out);
}

// round 16
// speedup vs baseline: 1.9553x; 1.4500x over previous
#include <cuda_runtime.h>
#include <cuda_bf16.h>
#include <cstdint>
#include <cstddef>

#define BATCH 32
#define SEQ   512
#define ISZ   512
#define HSZ   1024
#define G4    4096
#define NB2   128
#define NT2   256

typedef unsigned long long ull;

// ---------------------------------------------------------------------------
// Device scratch (allocation-free rule: __device__ globals).
// g_Xg : [s][b][4096] input projections + bias, fp32, 256MB.
// g_hbf: ping-pong hidden state as bf16 SPLITS: [ping][sp][b][k], 256KB.
//        h = sp0 + sp1 (hi + residual); written by the epilogue each step.
// g_Upk: per-block smem image of U^T bf16 splits, swizzle baked in:
//        elem idx = hb*65536 + sp*32768 + c32*1024 + ((k>>3)^(c32&7))*8 + (k&7)
//        value    = split_sp( u_gate[k][hb*8 + (c32&7)] ), gate = c32>>3.
// ---------------------------------------------------------------------------
__device__ float         g_Xg[(size_t)SEQ * BATCH * G4];
__device__ __nv_bfloat16 g_hbf[2][2][BATCH * HSZ];
__device__ __nv_bfloat16 g_Upk[(size_t)128 * 65536];
__device__ unsigned      g_cnt;

// ---------------------------------------------------------------------------
// f32x2 packed fp32 FMA (phase-1 GEMM only).
// ---------------------------------------------------------------------------
__device__ __forceinline__ void fma2(ull& d, ull a, ull b) {
    asm("fma.rn.f32x2 %0, %1, %2, %0;" : "+l"(d) : "l"(a), "l"(b));
}
__device__ __forceinline__ float2 upk(ull v) {
    float2 r; asm("mov.b64 {%0, %1}, %2;" : "=f"(r.x), "=f"(r.y) : "l"(v)); return r;
}

// cp.async 16B, L1-bypass (.cg).
__device__ __forceinline__ void cpa16(uint32_t saddr, const void* gptr) {
    asm volatile("cp.async.cg.shared.global [%0], [%1], 16;"
                 :: "r"(saddr), "l"(gptr) : "memory");
}
__device__ __forceinline__ void cpa_commit() {
    asm volatile("cp.async.commit_group;" ::: "memory");
}
__device__ __forceinline__ void cpa_wait1() {
    asm volatile("cp.async.wait_group 1;" ::: "memory");
}
__device__ __forceinline__ void cpa_wait0() {
    asm volatile("cp.async.wait_group 0;" ::: "memory");
}

__device__ __forceinline__ uint32_t smem_u32(const void* p) {
    uint32_t a;
    asm("{ .reg .u64 t; cvta.to.shared.u64 t, %1; cvt.u32.u64 %0, t; }"
        : "=r"(a) : "l"(p));
    return a;
}

// ldmatrix (sm_75+) and mma.sync bf16 (sm_80+) — compile under compute_103.
#define LDSM_X4(r0, r1, r2, r3, addr) \
    asm volatile("ldmatrix.sync.aligned.m8n8.x4.shared.b16 {%0,%1,%2,%3}, [%4];" \
                 : "=r"(r0), "=r"(r1), "=r"(r2), "=r"(r3) : "r"(addr))
#define LDSM_X2(r0, r1, addr) \
    asm volatile("ldmatrix.sync.aligned.m8n8.x2.shared.b16 {%0,%1}, [%2];" \
                 : "=r"(r0), "=r"(r1) : "r"(addr))
#define MMA16816(d0, d1, d2, d3, a0, a1, a2, a3, b0, b1) \
    asm volatile("mma.sync.aligned.m16n8k16.row.col.f32.bf16.bf16.f32 " \
                 "{%0,%1,%2,%3}, {%4,%5,%6,%7}, {%8,%9}, {%0,%1,%2,%3};" \
                 : "+f"(d0), "+f"(d1), "+f"(d2), "+f"(d3) \
                 : "r"(a0), "r"(a1), "r"(a2), "r"(a3), "r"(b0), "r"(b1))

// ---------------------------------------------------------------------------
// Init: zero h0 splits (both pings) and barrier counter (every graph replay).
// ---------------------------------------------------------------------------
__global__ void lstm_init() {
    unsigned t = blockIdx.x * blockDim.x + threadIdx.x;
    if (t == 0) g_cnt = 0u;
    unsigned stride = gridDim.x * blockDim.x;
    __nv_bfloat16 z = __float2bfloat16(0.f);
    for (unsigned i = t; i < BATCH * HSZ; i += stride) {
        g_hbf[0][0][i] = z; g_hbf[0][1][i] = z;
        g_hbf[1][0][i] = z; g_hbf[1][1][i] = z;
    }
}

// ---------------------------------------------------------------------------
// Pack U^T bf16 splits into the swizzled per-block smem image (see g_Upk).
// ---------------------------------------------------------------------------
__global__ __launch_bounds__(256)
void pack_umma(const float* __restrict__ u0, const float* __restrict__ u1,
               const float* __restrict__ u2, const float* __restrict__ u3)
{
    size_t idx = (size_t)blockIdx.x * 256 + threadIdx.x;   // 0..8388607
    int k   = (int)(idx & 1023);
    int c32 = (int)((idx >> 10) & 31);
    int sp  = (int)((idx >> 15) & 1);
    int hb  = (int)(idx >> 16);
    int gate = c32 >> 3;
    int unit = hb * 8 + (c32 & 7);
    const float* u = (gate == 0) ? u0 : (gate == 1) ? u1 : (gate == 2) ? u2 : u3;
    float v = u[(size_t)k * HSZ + unit];
    __nv_bfloat16 hi = __float2bfloat16(v);
    __nv_bfloat16 val = sp ? __float2bfloat16(v - __bfloat162float(hi)) : hi;
    size_t dst = (size_t)hb * 65536 + (size_t)sp * 32768 + (size_t)c32 * 1024
               + (size_t)(((k >> 3) ^ (c32 & 7)) * 8) + (k & 7);
    g_Upk[dst] = val;
}

// ---------------------------------------------------------------------------
// Phase 1: Xg = X @ [Wi|Wf|Wc|Wo] + b  (known-good; unchanged).
// ---------------------------------------------------------------------------
__global__ __launch_bounds__(256, 2)
void xg_gemm(const float* __restrict__ X,
             const float* __restrict__ w0, const float* __restrict__ w1,
             const float* __restrict__ w2, const float* __restrict__ w3,
             const float* __restrict__ bi0, const float* __restrict__ bi1,
             const float* __restrict__ bi2, const float* __restrict__ bi3)
{
    __shared__ float2 As2[16 * 128];
    __shared__ float  Bs [16 * 128];

    const int tid  = threadIdx.x;
    const int n0   = blockIdx.x * 128;
    const int m0   = blockIdx.y * 128;
    const int gate = blockIdx.x >> 3;
    const float* W  = (gate == 0) ? w0 : (gate == 1) ? w1 : (gate == 2) ? w2 : w3;
    const float* Bv = (gate == 0) ? bi0 : (gate == 1) ? bi1 : (gate == 2) ? bi2 : bi3;
    const int nloc = n0 & 1023;

    const int ar  = tid & 127;
    const int as4 = tid >> 7;
    const int mg  = m0 + ar;
    const float* Xrow = X + ((size_t)(mg & 31) * SEQ + (size_t)(mg >> 5)) * ISZ;

    const int bn4 = (tid & 31) * 4;
    const int bkr = tid >> 5;
    const int tx = tid & 15, ty = tid >> 4;

    ull acc[8][4];
    #pragma unroll
    for (int i = 0; i < 8; ++i)
        #pragma unroll
        for (int j = 0; j < 4; ++j) acc[i][j] = 0ULL;

    for (int kt = 0; kt < ISZ; kt += 16) {
        float4 a0 = *(const float4*)(Xrow + kt + as4 * 4);
        float4 a1 = *(const float4*)(Xrow + kt + (as4 + 2) * 4);
        float4 b0 = *(const float4*)(W + (size_t)(kt + bkr)     * HSZ + nloc + bn4);
        float4 b1 = *(const float4*)(W + (size_t)(kt + bkr + 8) * HSZ + nloc + bn4);

        __syncthreads();
        As2[(as4 * 4 + 0) * 128 + ar] = make_float2(a0.x, a0.x);
        As2[(as4 * 4 + 1) * 128 + ar] = make_float2(a0.y, a0.y);
        As2[(as4 * 4 + 2) * 128 + ar] = make_float2(a0.z, a0.z);
        As2[(as4 * 4 + 3) * 128 + ar] = make_float2(a0.w, a0.w);
        As2[((as4 + 2) * 4 + 0) * 128 + ar] = make_float2(a1.x, a1.x);
        As2[((as4 + 2) * 4 + 1) * 128 + ar] = make_float2(a1.y, a1.y);
        As2[((as4 + 2) * 4 + 2) * 128 + ar] = make_float2(a1.z, a1.z);
        As2[((as4 + 2) * 4 + 3) * 128 + ar] = make_float2(a1.w, a1.w);
        *(float4*)(Bs + bkr * 128 + bn4)       = b0;
        *(float4*)(Bs + (bkr + 8) * 128 + bn4) = b1;
        __syncthreads();

        #pragma unroll
        for (int k = 0; k < 16; ++k) {
            ull a[8], bb[4];
            ulonglong2 p;
            p = *(const ulonglong2*)(As2 + k * 128 + ty * 8);     a[0] = p.x; a[1] = p.y;
            p = *(const ulonglong2*)(As2 + k * 128 + ty * 8 + 2); a[2] = p.x; a[3] = p.y;
            p = *(const ulonglong2*)(As2 + k * 128 + ty * 8 + 4); a[4] = p.x; a[5] = p.y;
            p = *(const ulonglong2*)(As2 + k * 128 + ty * 8 + 6); a[6] = p.x; a[7] = p.y;
            p = *(const ulonglong2*)(Bs + k * 128 + tx * 8);      bb[0] = p.x; bb[1] = p.y;
            p = *(const ulonglong2*)(Bs + k * 128 + tx * 8 + 4);  bb[2] = p.x; bb[3] = p.y;
            #pragma unroll
            for (int i = 0; i < 8; ++i)
                #pragma unroll
                for (int j = 0; j < 4; ++j) fma2(acc[i][j], a[i], bb[j]);
        }
    }

    float4 bb0 = *(const float4*)(Bv + nloc + tx * 8);
    float4 bb1 = *(const float4*)(Bv + nloc + tx * 8 + 4);
    #pragma unroll
    for (int i = 0; i < 8; ++i) {
        float2 c0 = upk(acc[i][0]), c1 = upk(acc[i][1]);
        float2 c2 = upk(acc[i][2]), c3 = upk(acc[i][3]);
        float4 o0 = make_float4(c0.x + bb0.x, c0.y + bb0.y, c1.x + bb0.z, c1.y + bb0.w);
        float4 o1 = make_float4(c2.x + bb1.x, c2.y + bb1.y, c3.x + bb1.z, c3.y + bb1.w);
        size_t row = (size_t)(m0 + ty * 8 + i) * G4 + n0 + tx * 8;
        *(float4*)(g_Xg + row)     = o0;
        *(float4*)(g_Xg + row + 4) = o1;
    }
}

// ---------------------------------------------------------------------------
// Phase 2: mma.sync (HMMA bf16) recurrence. Block hb: 32 gate-cols x 32
// batches, K=1024. 8 warps = 8 m16n8 output tiles (mh = w&1 -> m0, nq = w>>1
// -> b0), each over full K. Split precision: D = U0·h0 + U1·h0 + U0·h1.
// U splits smem-resident (128KB, XOR-swizzled, conflict-free ldmatrix);
// h splits staged per step in four 32KB cp.async chunks, double-buffered.
// Epilogue reads D tile from Gs, adds Xg, applies gates, writes h splits.
// One grid barrier per step. smem: Us 128K + Hs 64K + Gs 4K + XgS 8K = 204K.
// ---------------------------------------------------------------------------
#define OFF_HS  131072
#define OFF_GS  196608
#define OFF_XG  200704
#define SMEM_P2 208896

// Stage h chunk c (k range c*256..+255, both splits, 32KB) into buffer buf.
#define STAGE(buf, c) do {                                                    \
    _Pragma("unroll")                                                         \
    for (int i_ = 0; i_ < 8; ++i_) {                                          \
        int id_ = i_ * 256 + tid;                                             \
        int sp_ = id_ >> 10;                                                  \
        int b_  = (id_ >> 5) & 31;                                            \
        int g_  = id_ & 31;                                                   \
        const __nv_bfloat16* src_ = g_hbf[cur][sp_] + b_ * 1024 + (c) * 256 + g_ * 8; \
        uint32_t dst_ = smb + OFF_HS + (buf) * 32768 + sp_ * 16384            \
                      + b_ * 512 + (uint32_t)((g_ ^ (b_ & 7)) << 4);          \
        cpa16(dst_, src_);                                                    \
    }                                                                         \
} while (0)

// Compute chunk c (16 k-steps of 16) from buffer buf.
#define CHUNK(buf, c) do {                                                    \
    uint32_t hbase_ = smb + OFF_HS + (buf) * 32768 + rowB * 512;              \
    _Pragma("unroll")                                                         \
    for (int ks_ = 0; ks_ < 16; ++ks_) {                                      \
        uint32_t kgA_ = (uint32_t)((c) * 32 + ks_ * 2) + (lane >> 4);         \
        uint32_t aad_ = abase + (((kgA_ ^ rk) << 4));                         \
        uint32_t a0_, a1_, a2_, a3_, e0_, e1_, e2_, e3_, h0_, h1_, r0_, r1_;  \
        LDSM_X4(a0_, a1_, a2_, a3_, aad_);                                    \
        LDSM_X4(e0_, e1_, e2_, e3_, aad_ + 65536);                            \
        uint32_t kgB_ = (uint32_t)(ks_ * 2) + ((lane >> 3) & 1);              \
        uint32_t bad_ = hbase_ + (((kgB_ ^ rkB) << 4));                       \
        LDSM_X2(h0_, h1_, bad_);                                              \
        LDSM_X2(r0_, r1_, bad_ + 16384);                                      \
        MMA16816(d0, d1, d2, d3, a0_, a1_, a2_, a3_, h0_, h1_);               \
        MMA16816(d0, d1, d2, d3, e0_, e1_, e2_, e3_, h0_, h1_);               \
        MMA16816(d0, d1, d2, d3, a0_, a1_, a2_, a3_, r0_, r1_);               \
    }                                                                         \
} while (0)

__global__ __launch_bounds__(NT2, 1)
void lstm_rec(float* __restrict__ out)
{
    extern __shared__ char sm[];
    float* Gs  = (float*)(sm + OFF_GS);     // [b][c32], 4KB
    float* XgS = (float*)(sm + OFF_XG);     // 2 x [b][32], 8KB
    const uint32_t smb = smem_u32(sm);

    const int tid  = threadIdx.x;
    const int hb   = blockIdx.x;
    const int w    = tid >> 5;
    const int lane = tid & 31;
    const int m0   = (w & 1) * 16;          // col-half of this warp's tile
    const int b0   = (w >> 1) * 8;          // batch-octet

    // ldmatrix lane roles (constant per thread)
    const uint32_t rowA = (uint32_t)(m0 + (lane & 15));
    const uint32_t rk   = (uint32_t)(lane & 7);
    const uint32_t rowB = (uint32_t)(b0 + (lane & 7));
    const uint32_t rkB  = (uint32_t)(lane & 7);
    const uint32_t abase = smb + rowA * 2048;

    // D-fragment epilogue indices
    const int grp = lane >> 2, tig = lane & 3;

    // gate-epilogue role
    const int ub = tid >> 3, j = tid & 7;
    const int kglob = hb * 8 + j;
    float creg = 0.f;

    // Xg staging role
    const int xb = tid >> 3, xq = tid & 7;
    const size_t xgcol = (size_t)(xq >> 1) * 1024 + hb * 8 + (xq & 1) * 4;
    const uint32_t XgA = smb + OFF_XG;

    float* out_h = out + (size_t)BATCH * SEQ * HSZ;
    float* out_c = out_h + BATCH * HSZ;

    // one-time: copy this block's swizzled U image (128KB) into smem
    {
        const float4* src = (const float4*)(g_Upk + (size_t)hb * 65536);
        float4* dst = (float4*)sm;
        #pragma unroll 8
        for (int i = tid; i < 8192; i += NT2) dst[i] = src[i];
    }
    __syncthreads();

    int cur = 0;
    for (int s = 0; s < SEQ; ++s) {
        // --- stage chunks 0,1 (+ step-0 Xg) ---
        STAGE(0, 0);
        if (s == 0)
            cpa16(XgA + (uint32_t)((xb * 32 + xq * 4) * 4),
                  g_Xg + (size_t)xb * G4 + xgcol);
        cpa_commit();                               // G1 = c0 (+X0 once)
        STAGE(1, 1); cpa_commit();                  // G2 = c1

        float d0 = 0.f, d1 = 0.f, d2 = 0.f, d3 = 0.f;

        cpa_wait1(); __syncthreads();               // c0 ready
        CHUNK(0, 0);
        __syncthreads();                            // close WAR on buf0
        STAGE(0, 2);
        {
            int sn = (s + 1 < SEQ) ? s + 1 : SEQ - 1;
            cpa16(XgA + (uint32_t)((((s + 1) & 1) * 1024 + xb * 32 + xq * 4) * 4),
                  g_Xg + ((size_t)sn * BATCH + xb) * G4 + xgcol);
        }
        cpa_commit();                               // G3 = c2 + X_{s+1}

        cpa_wait1(); __syncthreads();               // c1 ready
        CHUNK(1, 1);
        __syncthreads();                            // close WAR on buf1
        STAGE(1, 3); cpa_commit();                  // G4 = c3

        cpa_wait1(); __syncthreads();               // c2 (+Xg) ready
        CHUNK(0, 2);

        cpa_wait0(); __syncthreads();               // c3 ready
        CHUNK(1, 3);

        // --- D fragments -> Gs[b][c32] ---
        Gs[(b0 + 2 * tig)     * 32 + m0 + grp]     = d0;
        Gs[(b0 + 2 * tig + 1) * 32 + m0 + grp]     = d1;
        Gs[(b0 + 2 * tig)     * 32 + m0 + 8 + grp] = d2;
        Gs[(b0 + 2 * tig + 1) * 32 + m0 + 8 + grp] = d3;
        __syncthreads();

        // --- gates + state update (role: ub, j) ---
        {
            const float* Xc = XgS + (s & 1) * 1024;
            float gi = Gs[ub * 32 + j]      + Xc[ub * 32 + j];
            float gf = Gs[ub * 32 + 8 + j]  + Xc[ub * 32 + 8 + j];
            float gc = Gs[ub * 32 + 16 + j] + Xc[ub * 32 + 16 + j];
            float go = Gs[ub * 32 + 24 + j] + Xc[ub * 32 + 24 + j];
            float it = 1.f / (1.f + __expf(-gi));
            float ft = 1.f / (1.f + __expf(-gf));
            float ct = tanhf(gc);
            float ot = 1.f / (1.f + __expf(-go));
            creg = ft * creg + it * ct;
            float hn = ot * tanhf(creg);
            __nv_bfloat16 hhi = __float2bfloat16(hn);
            __nv_bfloat16 hlo = __float2bfloat16(hn - __bfloat162float(hhi));
            g_hbf[cur ^ 1][0][ub * HSZ + kglob] = hhi;
            g_hbf[cur ^ 1][1][ub * HSZ + kglob] = hlo;
            out[((size_t)ub * SEQ + s) * HSZ + kglob] = hn;
            if (s == SEQ - 1) {
                out_h[ub * HSZ + kglob] = hn;
                out_c[ub * HSZ + kglob] = creg;
            }
        }

        // --- grid barrier: release-add + acquire-spin ---
        __syncthreads();
        if (tid == 0) {
            unsigned old;
            asm volatile("atom.add.release.gpu.u32 %0, [%1], 1;"
                         : "=r"(old) : "l"(&g_cnt) : "memory");
            unsigned target = (unsigned)NB2 * (unsigned)(s + 1);
            unsigned v;
            do {
                asm volatile("ld.acquire.gpu.u32 %0, [%1];"
                             : "=r"(v) : "l"(&g_cnt) : "memory");
            } while (v < target);
        }
        __syncthreads();
        cur ^= 1;
    }
}

// ---------------------------------------------------------------------------
// Launch. Inputs: X, w_i,u_i,b_i, w_f,u_f,b_f, w_c,u_c,b_c, w_o,u_o,b_o.
// Output: [hidden_seq (B,S,H) | h_T (B,H) | c_T (B,H)] fp32.
// ---------------------------------------------------------------------------
extern "C" void kernel_launch(void* const* d_in, const int* in_sizes, int n_in,
                              void* d_out, int out_size) {
    (void)in_sizes; (void)n_in; (void)out_size;
    const float* X   = (const float*)d_in[0];
    const float* w_i = (const float*)d_in[1];
    const float* u_i = (const float*)d_in[2];
    const float* b_i = (const float*)d_in[3];
    const float* w_f = (const float*)d_in[4];
    const float* u_f = (const float*)d_in[5];
    const float* b_f = (const float*)d_in[6];
    const float* w_c = (const float*)d_in[7];
    const float* u_c = (const float*)d_in[8];
    const float* b_c = (const float*)d_in[9];
    const float* w_o = (const float*)d_in[10];
    const float* u_o = (const float*)d_in[11];
    const float* b_o = (const float*)d_in[12];
    float* out = (float*)d_out;

    lstm_init<<<64, 256>>>();
    pack_umma<<<32768, 256>>>(u_i, u_f, u_c, u_o);

    dim3 g1(32, 128);   // N/128 x M/128
    xg_gemm<<<g1, 256>>>(X, w_i, w_f, w_c, w_o, b_i, b_f, b_c, b_o);

    cudaFuncSetAttribute(lstm_rec, cudaFuncAttributeMaxDynamicSharedMemorySize,
                         SMEM_P2);
    lstm_rec<<<NB2, NT2, SMEM_P2>>>(out);
}

// round 17
// speedup vs baseline: 2.5425x; 1.3003x over previous
#include <cuda_runtime.h>
#include <cuda_bf16.h>
#include <cstdint>
#include <cstddef>

#define BATCH 32
#define SEQ   512
#define ISZ   512
#define HSZ   1024
#define G4    4096
#define NB2   128
#define NT2   256

typedef unsigned long long ull;

// ---------------------------------------------------------------------------
// Device scratch (allocation-free rule: __device__ globals).
// g_Xg : [s][b][4096] input projections + bias, fp32, 256MB.
// g_hbf: ping-pong hidden state as bf16 SPLITS: [ping][sp][b][k], 256KB.
// g_Upk: per-block smem image of U^T bf16 splits (swizzle baked in), 16MB.
// g_Xbf: bf16 splits of X, [sp][m(16384)][k(512)], m = s*32+b, 32MB.
// g_Wbf: bf16 splits of [Wi|Wf|Wc|Wo]^T, [sp][n(4096)][k(512)], 8MB.
// g_bias: concatenated bias [4096].
// ---------------------------------------------------------------------------
__device__ float         g_Xg[(size_t)SEQ * BATCH * G4];
__device__ __nv_bfloat16 g_hbf[2][2][BATCH * HSZ];
__device__ __nv_bfloat16 g_Upk[(size_t)128 * 65536];
__device__ __nv_bfloat16 g_Xbf[(size_t)2 * 16384 * 512];
__device__ __nv_bfloat16 g_Wbf[(size_t)2 * 4096 * 512];
__device__ float         g_bias[G4];
__device__ unsigned      g_cnt;

// cp.async 16B, L1-bypass (.cg).
__device__ __forceinline__ void cpa16(uint32_t saddr, const void* gptr) {
    asm volatile("cp.async.cg.shared.global [%0], [%1], 16;"
                 :: "r"(saddr), "l"(gptr) : "memory");
}
__device__ __forceinline__ void cpa_commit() {
    asm volatile("cp.async.commit_group;" ::: "memory");
}
__device__ __forceinline__ void cpa_wait1() {
    asm volatile("cp.async.wait_group 1;" ::: "memory");
}
__device__ __forceinline__ void cpa_wait0() {
    asm volatile("cp.async.wait_group 0;" ::: "memory");
}
__device__ __forceinline__ uint32_t smem_u32(const void* p) {
    uint32_t a;
    asm("{ .reg .u64 t; cvta.to.shared.u64 t, %1; cvt.u32.u64 %0, t; }"
        : "=r"(a) : "l"(p));
    return a;
}

// ldmatrix (sm_75+) and mma.sync bf16 (sm_80+) — compile under compute_103.
#define LDSM_X4(r0, r1, r2, r3, addr) \
    asm volatile("ldmatrix.sync.aligned.m8n8.x4.shared.b16 {%0,%1,%2,%3}, [%4];" \
                 : "=r"(r0), "=r"(r1), "=r"(r2), "=r"(r3) : "r"(addr))
#define LDSM_X2(r0, r1, addr) \
    asm volatile("ldmatrix.sync.aligned.m8n8.x2.shared.b16 {%0,%1}, [%2];" \
                 : "=r"(r0), "=r"(r1) : "r"(addr))
#define MMA16816(d0, d1, d2, d3, a0, a1, a2, a3, b0, b1) \
    asm volatile("mma.sync.aligned.m16n8k16.row.col.f32.bf16.bf16.f32 " \
                 "{%0,%1,%2,%3}, {%4,%5,%6,%7}, {%8,%9}, {%0,%1,%2,%3};" \
                 : "+f"(d0), "+f"(d1), "+f"(d2), "+f"(d3) \
                 : "r"(a0), "r"(a1), "r"(a2), "r"(a3), "r"(b0), "r"(b1))

// ---------------------------------------------------------------------------
// Init: zero h0 splits (both pings) and barrier counter (every graph replay).
// ---------------------------------------------------------------------------
__global__ void lstm_init() {
    unsigned t = blockIdx.x * blockDim.x + threadIdx.x;
    if (t == 0) g_cnt = 0u;
    unsigned stride = gridDim.x * blockDim.x;
    __nv_bfloat16 z = __float2bfloat16(0.f);
    for (unsigned i = t; i < BATCH * HSZ; i += stride) {
        g_hbf[0][0][i] = z; g_hbf[0][1][i] = z;
        g_hbf[1][0][i] = z; g_hbf[1][1][i] = z;
    }
}

// ---------------------------------------------------------------------------
// Pack U^T bf16 splits (swizzled per-block image) — unchanged from R16.
// ---------------------------------------------------------------------------
__global__ __launch_bounds__(256)
void pack_umma(const float* __restrict__ u0, const float* __restrict__ u1,
               const float* __restrict__ u2, const float* __restrict__ u3)
{
    size_t idx = (size_t)blockIdx.x * 256 + threadIdx.x;   // 0..8388607
    int k   = (int)(idx & 1023);
    int c32 = (int)((idx >> 10) & 31);
    int sp  = (int)((idx >> 15) & 1);
    int hb  = (int)(idx >> 16);
    int gate = c32 >> 3;
    int unit = hb * 8 + (c32 & 7);
    const float* u = (gate == 0) ? u0 : (gate == 1) ? u1 : (gate == 2) ? u2 : u3;
    float v = u[(size_t)k * HSZ + unit];
    __nv_bfloat16 hi = __float2bfloat16(v);
    __nv_bfloat16 val = sp ? __float2bfloat16(v - __bfloat162float(hi)) : hi;
    size_t dst = (size_t)hb * 65536 + (size_t)sp * 32768 + (size_t)c32 * 1024
               + (size_t)(((k >> 3) ^ (c32 & 7)) * 8) + (k & 7);
    g_Upk[dst] = val;
}

// ---------------------------------------------------------------------------
// Pack X bf16 splits: g_Xbf[sp][m][k], m = s*32+b, value X[b][s][k].
// ---------------------------------------------------------------------------
__global__ __launch_bounds__(256)
void pack_xbf(const float* __restrict__ X)
{
    size_t idx = (size_t)blockIdx.x * 256 + threadIdx.x;   // 0..2^24-1
    int k  = (int)(idx & 511);
    int m  = (int)((idx >> 9) & 16383);
    int sp = (int)(idx >> 23);
    int b = m & 31, s = m >> 5;
    float v = X[((size_t)b * SEQ + s) * ISZ + k];
    __nv_bfloat16 hi = __float2bfloat16(v);
    g_Xbf[idx] = sp ? __float2bfloat16(v - __bfloat162float(hi)) : hi;
}

// ---------------------------------------------------------------------------
// Pack W^T bf16 splits: g_Wbf[sp][n][k] = w_gate[k][n&1023]; also g_bias.
// ---------------------------------------------------------------------------
__global__ __launch_bounds__(256)
void pack_wbf(const float* __restrict__ w0, const float* __restrict__ w1,
              const float* __restrict__ w2, const float* __restrict__ w3,
              const float* __restrict__ bi0, const float* __restrict__ bi1,
              const float* __restrict__ bi2, const float* __restrict__ bi3)
{
    size_t idx = (size_t)blockIdx.x * 256 + threadIdx.x;   // 0..2^22-1
    int k  = (int)(idx & 511);
    int n  = (int)((idx >> 9) & 4095);
    int sp = (int)(idx >> 21);
    int gate = n >> 10, unit = n & 1023;
    const float* w = (gate == 0) ? w0 : (gate == 1) ? w1 : (gate == 2) ? w2 : w3;
    float v = w[(size_t)k * HSZ + unit];
    __nv_bfloat16 hi = __float2bfloat16(v);
    g_Wbf[idx] = sp ? __float2bfloat16(v - __bfloat162float(hi)) : hi;
    if (sp == 0 && k == 0) {
        const float* bv = (gate == 0) ? bi0 : (gate == 1) ? bi1
                        : (gate == 2) ? bi2 : bi3;
        g_bias[n] = bv[unit];
    }
}

// ---------------------------------------------------------------------------
// Phase 1 (tensor): Xg = X @ [W]^T + b via split-bf16 mma.sync.
// Block = 64 m-rows x 64 n-cols, K=512 in four 128-k chunks, double-buffered.
// 8 warps: wm = (w&3)*16, wn = (w>>2)*32 (4 m16n8 tiles n-wise).
// smem: A[2][128rows(64m x 2sp)][256B] + B[2][128rows(64n x 2sp)][256B] =128KB.
// Products: X0·W0 + X1·W0 + X0·W1 (fp32 accum; X1·W1 dropped).
// ---------------------------------------------------------------------------
#define XSM_B   65536
#define XSM_TOT 131072

#define XSTAGE(buf, c) do {                                                   \
    _Pragma("unroll")                                                         \
    for (int i_ = 0; i_ < 8; ++i_) {                                          \
        int id_ = i_ * 256 + tid;                                             \
        int row_ = id_ >> 4, g_ = id_ & 15;                                   \
        int sp_ = row_ >> 6, l_ = row_ & 63;                                  \
        cpa16(smb + (buf) * 32768 + row_ * 256 + ((g_ ^ (row_ & 7)) << 4),    \
              g_Xbf + (size_t)sp_ * 8388608 + (size_t)(m0 + l_) * 512         \
                    + (c) * 128 + g_ * 8);                                    \
    }                                                                         \
    _Pragma("unroll")                                                         \
    for (int i_ = 0; i_ < 8; ++i_) {                                          \
        int id_ = i_ * 256 + tid;                                             \
        int row_ = id_ >> 4, g_ = id_ & 15;                                   \
        int sp_ = row_ >> 6, l_ = row_ & 63;                                  \
        cpa16(smb + XSM_B + (buf) * 32768 + row_ * 256                        \
                  + ((g_ ^ (row_ & 7)) << 4),                                 \
              g_Wbf + (size_t)sp_ * 2097152 + (size_t)(n0 + l_) * 512         \
                    + (c) * 128 + g_ * 8);                                    \
    }                                                                         \
} while (0)

__global__ __launch_bounds__(256, 1)
void xg_mma()
{
    extern __shared__ char xsm[];
    const uint32_t smb = smem_u32(xsm);
    const int tid  = threadIdx.x;
    const int w    = tid >> 5;
    const int lane = tid & 31;
    const int n0   = blockIdx.x * 64;
    const int m0   = blockIdx.y * 64;
    const int wm   = (w & 3) * 16;
    const int wn   = (w >> 2) * 32;
    const int grp  = lane >> 2, tig = lane & 3;

    const uint32_t rk   = (uint32_t)(lane & 7);
    const uint32_t kofA = (uint32_t)(lane >> 4);
    const uint32_t kofB = (uint32_t)((lane >> 3) & 1);
    const uint32_t arow = (uint32_t)(wm + (lane & 15)) * 256;

    float acc[4][4];
    #pragma unroll
    for (int t = 0; t < 4; ++t)
        #pragma unroll
        for (int i = 0; i < 4; ++i) acc[t][i] = 0.f;

    XSTAGE(0, 0); cpa_commit();
    #pragma unroll 1
    for (int c = 0; c < 4; ++c) {
        if (c < 3) { XSTAGE((c + 1) & 1, c + 1); cpa_commit(); cpa_wait1(); }
        else       cpa_wait0();
        __syncthreads();
        uint32_t Abase = smb + (c & 1) * 32768 + arow;
        uint32_t Bb0   = smb + XSM_B + (c & 1) * 32768;
        #pragma unroll
        for (int ks = 0; ks < 8; ++ks) {
            uint32_t a0, a1, a2, a3, e0, e1, e2, e3;
            uint32_t aad = Abase + (((ks * 2 + kofA) ^ rk) << 4);
            LDSM_X4(a0, a1, a2, a3, aad);
            LDSM_X4(e0, e1, e2, e3, aad + 16384);
            uint32_t boff = (((ks * 2 + kofB) ^ rk) << 4);
            #pragma unroll
            for (int t = 0; t < 4; ++t) {
                uint32_t bad = Bb0 + (uint32_t)(wn + t * 8 + (lane & 7)) * 256 + boff;
                uint32_t b0, b1, r0, r1;
                LDSM_X2(b0, b1, bad);
                LDSM_X2(r0, r1, bad + 16384);
                MMA16816(acc[t][0], acc[t][1], acc[t][2], acc[t][3],
                         a0, a1, a2, a3, b0, b1);
                MMA16816(acc[t][0], acc[t][1], acc[t][2], acc[t][3],
                         e0, e1, e2, e3, b0, b1);
                MMA16816(acc[t][0], acc[t][1], acc[t][2], acc[t][3],
                         a0, a1, a2, a3, r0, r1);
            }
        }
        __syncthreads();
    }

    // epilogue: add bias, write fp32 (float2 per row-pair)
    #pragma unroll
    for (int t = 0; t < 4; ++t) {
        int ng = n0 + wn + t * 8 + 2 * tig;
        int mg = m0 + wm + grp;
        float b0v = g_bias[ng], b1v = g_bias[ng + 1];
        float2 v01 = make_float2(acc[t][0] + b0v, acc[t][1] + b1v);
        float2 v23 = make_float2(acc[t][2] + b0v, acc[t][3] + b1v);
        *(float2*)(g_Xg + (size_t)mg * G4 + ng)       = v01;
        *(float2*)(g_Xg + (size_t)(mg + 8) * G4 + ng) = v23;
    }
}

// ---------------------------------------------------------------------------
// Phase 2: mma.sync recurrence (R16-proven), now with THREE independent
// accumulator sets (dA/dB/dC, one per split product) to break the RAW chain.
// ---------------------------------------------------------------------------
#define OFF_HS  131072
#define OFF_GS  196608
#define OFF_XG  200704
#define SMEM_P2 208896

#define STAGE(buf, c) do {                                                    \
    _Pragma("unroll")                                                         \
    for (int i_ = 0; i_ < 8; ++i_) {                                          \
        int id_ = i_ * 256 + tid;                                             \
        int sp_ = id_ >> 10;                                                  \
        int b_  = (id_ >> 5) & 31;                                            \
        int g_  = id_ & 31;                                                   \
        const __nv_bfloat16* src_ = g_hbf[cur][sp_] + b_ * 1024 + (c) * 256 + g_ * 8; \
        uint32_t dst_ = smb + OFF_HS + (buf) * 32768 + sp_ * 16384            \
                      + b_ * 512 + (uint32_t)((g_ ^ (b_ & 7)) << 4);          \
        cpa16(dst_, src_);                                                    \
    }                                                                         \
} while (0)

#define CHUNK(buf, c) do {                                                    \
    uint32_t hbase_ = smb + OFF_HS + (buf) * 32768 + rowB * 512;              \
    _Pragma("unroll")                                                         \
    for (int ks_ = 0; ks_ < 16; ++ks_) {                                      \
        uint32_t kgA_ = (uint32_t)((c) * 32 + ks_ * 2) + (lane >> 4);         \
        uint32_t aad_ = abase + (((kgA_ ^ rk) << 4));                         \
        uint32_t a0_, a1_, a2_, a3_, e0_, e1_, e2_, e3_, h0_, h1_, r0_, r1_;  \
        LDSM_X4(a0_, a1_, a2_, a3_, aad_);                                    \
        LDSM_X4(e0_, e1_, e2_, e3_, aad_ + 65536);                            \
        uint32_t kgB_ = (uint32_t)(ks_ * 2) + ((lane >> 3) & 1);              \
        uint32_t bad_ = hbase_ + (((kgB_ ^ rkB) << 4));                       \
        LDSM_X2(h0_, h1_, bad_);                                              \
        LDSM_X2(r0_, r1_, bad_ + 16384);                                      \
        MMA16816(dA[0], dA[1], dA[2], dA[3], a0_, a1_, a2_, a3_, h0_, h1_);   \
        MMA16816(dB[0], dB[1], dB[2], dB[3], e0_, e1_, e2_, e3_, h0_, h1_);   \
        MMA16816(dC[0], dC[1], dC[2], dC[3], a0_, a1_, a2_, a3_, r0_, r1_);   \
    }                                                                         \
} while (0)

__global__ __launch_bounds__(NT2, 1)
void lstm_rec(float* __restrict__ out)
{
    extern __shared__ char sm[];
    float* Gs  = (float*)(sm + OFF_GS);     // [b][c32], 4KB
    float* XgS = (float*)(sm + OFF_XG);     // 2 x [b][32], 8KB
    const uint32_t smb = smem_u32(sm);

    const int tid  = threadIdx.x;
    const int hb   = blockIdx.x;
    const int w    = tid >> 5;
    const int lane = tid & 31;
    const int m0   = (w & 1) * 16;
    const int b0   = (w >> 1) * 8;

    const uint32_t rowA = (uint32_t)(m0 + (lane & 15));
    const uint32_t rk   = (uint32_t)(lane & 7);
    const uint32_t rowB = (uint32_t)(b0 + (lane & 7));
    const uint32_t rkB  = (uint32_t)(lane & 7);
    const uint32_t abase = smb + rowA * 2048;

    const int grp = lane >> 2, tig = lane & 3;

    const int ub = tid >> 3, j = tid & 7;
    const int kglob = hb * 8 + j;
    float creg = 0.f;

    const int xb = tid >> 3, xq = tid & 7;
    const size_t xgcol = (size_t)(xq >> 1) * 1024 + hb * 8 + (xq & 1) * 4;
    const uint32_t XgA = smb + OFF_XG;

    float* out_h = out + (size_t)BATCH * SEQ * HSZ;
    float* out_c = out_h + BATCH * HSZ;

    // one-time: copy this block's swizzled U image (128KB) into smem
    {
        const float4* src = (const float4*)(g_Upk + (size_t)hb * 65536);
        float4* dst = (float4*)sm;
        #pragma unroll 8
        for (int i = tid; i < 8192; i += NT2) dst[i] = src[i];
    }
    __syncthreads();

    int cur = 0;
    for (int s = 0; s < SEQ; ++s) {
        STAGE(0, 0);
        if (s == 0)
            cpa16(XgA + (uint32_t)((xb * 32 + xq * 4) * 4),
                  g_Xg + (size_t)xb * G4 + xgcol);
        cpa_commit();                               // G1 = c0 (+X0 once)
        STAGE(1, 1); cpa_commit();                  // G2 = c1

        float dA[4] = {0.f, 0.f, 0.f, 0.f};
        float dB[4] = {0.f, 0.f, 0.f, 0.f};
        float dC[4] = {0.f, 0.f, 0.f, 0.f};

        cpa_wait1(); __syncthreads();               // c0 ready
        CHUNK(0, 0);
        __syncthreads();                            // close WAR on buf0
        STAGE(0, 2);
        {
            int sn = (s + 1 < SEQ) ? s + 1 : SEQ - 1;
            cpa16(XgA + (uint32_t)((((s + 1) & 1) * 1024 + xb * 32 + xq * 4) * 4),
                  g_Xg + ((size_t)sn * BATCH + xb) * G4 + xgcol);
        }
        cpa_commit();                               // G3 = c2 + X_{s+1}

        cpa_wait1(); __syncthreads();               // c1 ready
        CHUNK(1, 1);
        __syncthreads();                            // close WAR on buf1
        STAGE(1, 3); cpa_commit();                  // G4 = c3

        cpa_wait1(); __syncthreads();               // c2 (+Xg) ready
        CHUNK(0, 2);

        cpa_wait0(); __syncthreads();               // c3 ready
        CHUNK(1, 3);

        // --- D fragments -> Gs[b][c32] ---
        Gs[(b0 + 2 * tig)     * 32 + m0 + grp]     = dA[0] + dB[0] + dC[0];
        Gs[(b0 + 2 * tig + 1) * 32 + m0 + grp]     = dA[1] + dB[1] + dC[1];
        Gs[(b0 + 2 * tig)     * 32 + m0 + 8 + grp] = dA[2] + dB[2] + dC[2];
        Gs[(b0 + 2 * tig + 1) * 32 + m0 + 8 + grp] = dA[3] + dB[3] + dC[3];
        __syncthreads();

        // --- gates + state update (role: ub, j) ---
        {
            const float* Xc = XgS + (s & 1) * 1024;
            float gi = Gs[ub * 32 + j]      + Xc[ub * 32 + j];
            float gf = Gs[ub * 32 + 8 + j]  + Xc[ub * 32 + 8 + j];
            float gc = Gs[ub * 32 + 16 + j] + Xc[ub * 32 + 16 + j];
            float go = Gs[ub * 32 + 24 + j] + Xc[ub * 32 + 24 + j];
            float it = 1.f / (1.f + __expf(-gi));
            float ft = 1.f / (1.f + __expf(-gf));
            float ct = tanhf(gc);
            float ot = 1.f / (1.f + __expf(-go));
            creg = ft * creg + it * ct;
            float hn = ot * tanhf(creg);
            __nv_bfloat16 hhi = __float2bfloat16(hn);
            __nv_bfloat16 hlo = __float2bfloat16(hn - __bfloat162float(hhi));
            g_hbf[cur ^ 1][0][ub * HSZ + kglob] = hhi;
            g_hbf[cur ^ 1][1][ub * HSZ + kglob] = hlo;
            out[((size_t)ub * SEQ + s) * HSZ + kglob] = hn;
            if (s == SEQ - 1) {
                out_h[ub * HSZ + kglob] = hn;
                out_c[ub * HSZ + kglob] = creg;
            }
        }

        // --- grid barrier: release-add + acquire-spin ---
        __syncthreads();
        if (tid == 0) {
            unsigned old;
            asm volatile("atom.add.release.gpu.u32 %0, [%1], 1;"
                         : "=r"(old) : "l"(&g_cnt) : "memory");
            unsigned target = (unsigned)NB2 * (unsigned)(s + 1);
            unsigned v;
            do {
                asm volatile("ld.acquire.gpu.u32 %0, [%1];"
                             : "=r"(v) : "l"(&g_cnt) : "memory");
            } while (v < target);
        }
        __syncthreads();
        cur ^= 1;
    }
}

// ---------------------------------------------------------------------------
// Launch. Inputs: X, w_i,u_i,b_i, w_f,u_f,b_f, w_c,u_c,b_c, w_o,u_o,b_o.
// Output: [hidden_seq (B,S,H) | h_T (B,H) | c_T (B,H)] fp32.
// ---------------------------------------------------------------------------
extern "C" void kernel_launch(void* const* d_in, const int* in_sizes, int n_in,
                              void* d_out, int out_size) {
    (void)in_sizes; (void)n_in; (void)out_size;
    const float* X   = (const float*)d_in[0];
    const float* w_i = (const float*)d_in[1];
    const float* u_i = (const float*)d_in[2];
    const float* b_i = (const float*)d_in[3];
    const float* w_f = (const float*)d_in[4];
    const float* u_f = (const float*)d_in[5];
    const float* b_f = (const float*)d_in[6];
    const float* w_c = (const float*)d_in[7];
    const float* u_c = (const float*)d_in[8];
    const float* b_c = (const float*)d_in[9];
    const float* w_o = (const float*)d_in[10];
    const float* u_o = (const float*)d_in[11];
    const float* b_o = (const float*)d_in[12];
    float* out = (float*)d_out;

    lstm_init<<<64, 256>>>();
    pack_umma<<<32768, 256>>>(u_i, u_f, u_c, u_o);
    pack_xbf<<<65536, 256>>>(X);
    pack_wbf<<<16384, 256>>>(w_i, w_f, w_c, w_o, b_i, b_f, b_c, b_o);

    cudaFuncSetAttribute(xg_mma, cudaFuncAttributeMaxDynamicSharedMemorySize,
                         XSM_TOT);
    xg_mma<<<dim3(64, 256), 256, XSM_TOT>>>();

    cudaFuncSetAttribute(lstm_rec, cudaFuncAttributeMaxDynamicSharedMemorySize,
                         SMEM_P2);
    lstm_rec<<<NB2, NT2, SMEM_P2>>>(out);
}